// round 7
// baseline (speedup 1.0000x reference)
#include <cuda_runtime.h>

static constexpr int NB = 128, NT = 1024, ND = 128, NH = 256, NHD = 128;

typedef unsigned long long ull;

// global persistent state
__device__ __align__(16) float g_h0[2][NB * NH];
__device__ __align__(16) float g_h1[2][NB * NH];
__device__ __align__(16) float g_hd0[2][NB * NHD];
__device__ __align__(16) float g_hd1[2][NB * NHD];
__device__ __align__(16) float g_xwd0[NB * 4 * NHD];
__device__ volatile unsigned g_ebar[4];
__device__ volatile unsigned g_dbar[4];

__device__ __forceinline__ void fma2(ull &acc, ull a, ull b) {
    asm("fma.rn.f32x2 %0, %1, %2, %0;" : "+l"(acc) : "l"(a), "l"(b));
}
__device__ __forceinline__ float hadd2(ull v) {
    float lo, hi;
    asm("mov.b64 {%0, %1}, %2;" : "=f"(lo), "=f"(hi) : "l"(v));
    return lo + hi;
}
__device__ __forceinline__ float sigf(float z) { return 1.0f / (1.0f + __expf(-z)); }
__device__ __forceinline__ float4 ldcg4(const float* p) {
    float4 v;
    asm volatile("ld.global.cg.v4.f32 {%0,%1,%2,%3}, [%4];"
                 : "=f"(v.x), "=f"(v.y), "=f"(v.z), "=f"(v.w) : "l"(p));
    return v;
}
// group barrier: monotonically increasing counter, 32 arrivals per superstep
__device__ __forceinline__ void group_barrier(volatile unsigned* bar, unsigned target) {
    __syncthreads();
    if (threadIdx.x == 0) {
        __threadfence();
        atomicAdd((unsigned*)bar, 1u);
        while (*bar < target) { }
        __threadfence();
    }
    __syncthreads();
}

__global__ void zero_state_kernel() {
    int i = blockIdx.x * blockDim.x + threadIdx.x;   // 65536 threads
    ((float*)g_h0)[i] = 0.f;
    ((float*)g_h1)[i] = 0.f;
    if (i < 2 * NB * NHD) { ((float*)g_hd0)[i] = 0.f; ((float*)g_hd1)[i] = 0.f; }
    if (i < 4) g_ebar[i] = 0u;
    else if (i < 8) g_dbar[i - 4] = 0u;
}

// =================== persistent encoder ===================
// 128 CTAs = 4 groups x 32 CTAs. Group handles 32 batch rows.
// CTA owns 8 h-units (x4 gates) of L0 AND of L1; weights SMEM-resident.
__global__ void __launch_bounds__(256, 1) enc_persist(
    const float* __restrict__ x,
    const float* __restrict__ eW0, const float* __restrict__ eU0,
    const float* __restrict__ eb0, const float* __restrict__ ec0,
    const float* __restrict__ eW1, const float* __restrict__ eU1,
    const float* __restrict__ eb1, const float* __restrict__ ec1)
{
    extern __shared__ float sm[];
    float* w0x  = sm;                    // 32 x 132
    float* w0h  = w0x + 32 * 132;        // 32 x 260
    float* w1i  = w0h + 32 * 260;        // 32 x 260
    float* w1h  = w1i + 32 * 260;        // 32 x 260
    float* xs   = w1h + 32 * 260;        // 32 x 132
    float* h0p  = xs  + 32 * 132;        // 32 x 260
    float* h1p  = h0p + 32 * 260;        // 32 x 260
    float* pre  = h1p + 32 * 260;        // 2 x 32 x 33
    float* cst  = pre + 2 * 32 * 33;     // 2 x 8 x 32
    float* bias = cst + 2 * 8 * 32;      // 64

    const int tid = threadIdx.x;
    const int grp = blockIdx.x >> 5;
    const int cta = blockIdx.x & 31;
    const int bg  = grp * 32;
    const int ub  = cta * 8;

    // weight load (rows indexed gate*8+unit)
    for (int idx = tid; idx < 32 * 128; idx += 256) {
        int row = idx >> 7, k = idx & 127;
        int grow = (row >> 3) * NH + ub + (row & 7);
        w0x[row * 132 + k] = eW0[grow * ND + k];
    }
    for (int idx = tid; idx < 32 * 256; idx += 256) {
        int row = idx >> 8, k = idx & 255;
        int grow = (row >> 3) * NH + ub + (row & 7);
        w0h[row * 260 + k] = eU0[grow * NH + k];
        w1i[row * 260 + k] = eW1[grow * NH + k];
        w1h[row * 260 + k] = eU1[grow * NH + k];
    }
    if (tid < 32) {
        int grow = (tid >> 3) * NH + ub + (tid & 7);
        bias[tid]      = eb0[grow] + ec0[grow];
        bias[32 + tid] = eb1[grow] + ec1[grow];
    }
    for (int idx = tid; idx < 2 * 8 * 32; idx += 256) cst[idx] = 0.f;
    __syncthreads();

    for (int s = 0; s <= NT; s++) {
        // ---- stage activations ----
        if (s < NT) {
            for (int idx = tid; idx < 32 * 32; idx += 256) {
                int row = idx >> 5, c4 = (idx & 31) << 2;
                *(float4*)&xs[row * 132 + c4] =
                    __ldg((const float4*)&x[((bg + row) * NT + s) * ND + c4]);
            }
        }
        {
            const float* h0g = g_h0[(s + 1) & 1];
            const float* h1g = g_h1[s & 1];
            for (int idx = tid; idx < 32 * 64; idx += 256) {
                int row = idx >> 6, c4 = (idx & 63) << 2;
                *(float4*)&h0p[row * 260 + c4] = ldcg4(&h0g[(bg + row) * NH + c4]);
                *(float4*)&h1p[row * 260 + c4] = ldcg4(&h1g[(bg + row) * NH + c4]);
            }
        }
        __syncthreads();

        // ---- gate pre-activations ----
        if ((tid >> 5) < 4) {                       // warps 0-3: layer 0, step s
            if (s < NT) {
                const int bs = tid & 7, rp = tid >> 3;
                const int r0 = rp * 2, r1 = rp * 2 + 1;
                ull acc[2][4][2] = {};
#pragma unroll 4
                for (int k = 0; k < ND; k += 4) {
                    ulonglong2 wa = *(const ulonglong2*)&w0x[r0 * 132 + k];
                    ulonglong2 wb = *(const ulonglong2*)&w0x[r1 * 132 + k];
#pragma unroll
                    for (int i = 0; i < 4; i++) {
                        ulonglong2 a = *(const ulonglong2*)&xs[(bs + 8 * i) * 132 + k];
                        fma2(acc[0][i][0], a.x, wa.x); fma2(acc[0][i][1], a.y, wa.y);
                        fma2(acc[1][i][0], a.x, wb.x); fma2(acc[1][i][1], a.y, wb.y);
                    }
                }
#pragma unroll 4
                for (int k = 0; k < NH; k += 4) {
                    ulonglong2 wa = *(const ulonglong2*)&w0h[r0 * 260 + k];
                    ulonglong2 wb = *(const ulonglong2*)&w0h[r1 * 260 + k];
#pragma unroll
                    for (int i = 0; i < 4; i++) {
                        ulonglong2 a = *(const ulonglong2*)&h0p[(bs + 8 * i) * 260 + k];
                        fma2(acc[0][i][0], a.x, wa.x); fma2(acc[0][i][1], a.y, wa.y);
                        fma2(acc[1][i][0], a.x, wb.x); fma2(acc[1][i][1], a.y, wb.y);
                    }
                }
#pragma unroll
                for (int i = 0; i < 4; i++) {
                    int b = bs + 8 * i;
                    pre[r0 * 33 + b] = hadd2(acc[0][i][0]) + hadd2(acc[0][i][1]) + bias[r0];
                    pre[r1 * 33 + b] = hadd2(acc[1][i][0]) + hadd2(acc[1][i][1]) + bias[r1];
                }
            }
        } else {                                    // warps 4-7: layer 1, step s-1
            if (s >= 1) {
                const int tl = tid - 128;
                const int bs = tl & 7, rp = tl >> 3;
                const int r0 = rp * 2, r1 = rp * 2 + 1;
                ull acc[2][4][2] = {};
#pragma unroll 4
                for (int k = 0; k < NH; k += 4) {
                    ulonglong2 wa = *(const ulonglong2*)&w1i[r0 * 260 + k];
                    ulonglong2 wb = *(const ulonglong2*)&w1i[r1 * 260 + k];
#pragma unroll
                    for (int i = 0; i < 4; i++) {
                        ulonglong2 a = *(const ulonglong2*)&h0p[(bs + 8 * i) * 260 + k];
                        fma2(acc[0][i][0], a.x, wa.x); fma2(acc[0][i][1], a.y, wa.y);
                        fma2(acc[1][i][0], a.x, wb.x); fma2(acc[1][i][1], a.y, wb.y);
                    }
                }
#pragma unroll 4
                for (int k = 0; k < NH; k += 4) {
                    ulonglong2 wa = *(const ulonglong2*)&w1h[r0 * 260 + k];
                    ulonglong2 wb = *(const ulonglong2*)&w1h[r1 * 260 + k];
#pragma unroll
                    for (int i = 0; i < 4; i++) {
                        ulonglong2 a = *(const ulonglong2*)&h1p[(bs + 8 * i) * 260 + k];
                        fma2(acc[0][i][0], a.x, wa.x); fma2(acc[0][i][1], a.y, wa.y);
                        fma2(acc[1][i][0], a.x, wb.x); fma2(acc[1][i][1], a.y, wb.y);
                    }
                }
#pragma unroll
                for (int i = 0; i < 4; i++) {
                    int b = bs + 8 * i;
                    pre[1056 + r0 * 33 + b] = hadd2(acc[0][i][0]) + hadd2(acc[0][i][1]) + bias[32 + r0];
                    pre[1056 + r1 * 33 + b] = hadd2(acc[1][i][0]) + hadd2(acc[1][i][1]) + bias[32 + r1];
                }
            }
        }
        __syncthreads();

        // ---- gate combine + state update ----
        {
            int layer = tid >> 7, q = tid & 127;
            int u0 = ((q >> 5) & 3) * 2, b = q & 31;
            bool ok = (layer == 0) ? (s < NT) : (s >= 1);
            if (ok) {
#pragma unroll
                for (int j = 0; j < 2; j++) {
                    int u = u0 + j;
                    float gi = pre[layer * 1056 + (0 * 8 + u) * 33 + b];
                    float gf = pre[layer * 1056 + (1 * 8 + u) * 33 + b];
                    float gg = pre[layer * 1056 + (2 * 8 + u) * 33 + b];
                    float go = pre[layer * 1056 + (3 * 8 + u) * 33 + b];
                    float c  = cst[layer * 256 + u * 32 + b];
                    float cv = sigf(gf) * c + sigf(gi) * tanhf(gg);
                    cst[layer * 256 + u * 32 + b] = cv;
                    float hv = sigf(go) * tanhf(cv);
                    int gidx = (bg + b) * NH + ub + u;
                    if (layer == 0) g_h0[s & 1][gidx] = hv;
                    else            g_h1[(s - 1) & 1][gidx] = hv;
                }
            }
        }
        group_barrier(&g_ebar[grp], 32u * (unsigned)(s + 1));
    }
}

// decoder L0 constant input projection: xwd0 = db0 + dc0 + hT @ dW0^T
__global__ void xwd0_kernel(const float* __restrict__ dW0,
                            const float* __restrict__ db0,
                            const float* __restrict__ dc0)
{
    int idx = blockIdx.x * blockDim.x + threadIdx.x;   // 65536
    int b = idx >> 9, gd = idx & 511;
    const float* hb = &g_h1[1][b * NH];                // h1[NT-1] lives in buf 1
    const float* wr = dW0 + gd * NH;
    ull a0 = 0ULL, a1 = 0ULL;
#pragma unroll 4
    for (int k = 0; k < NH; k += 4) {
        ulonglong2 hv = *(const ulonglong2*)&hb[k];
        ulonglong2 wv = *(const ulonglong2*)&wr[k];
        fma2(a0, hv.x, wv.x); fma2(a1, hv.y, wv.y);
    }
    g_xwd0[idx] = hadd2(a0) + hadd2(a1) + db0[gd] + dc0[gd];
}

// =================== persistent decoder ===================
__global__ void __launch_bounds__(256, 1) dec_persist(
    const float* __restrict__ dU0,
    const float* __restrict__ dW1, const float* __restrict__ dU1,
    const float* __restrict__ db1, const float* __restrict__ dc1,
    float* __restrict__ out)
{
    extern __shared__ float sm[];
    float* wd0h  = sm;                    // 16 x 132
    float* wd1i  = wd0h + 16 * 132;
    float* wd1h  = wd1i + 16 * 132;
    float* hd0p  = wd1h + 16 * 132;       // 32 x 132
    float* hd1p  = hd0p + 32 * 132;       // 32 x 132
    float* xw    = hd1p + 32 * 132;       // 32 x 17
    float* pre   = xw + 32 * 17;          // 2 x 16 x 33
    float* cst   = pre + 2 * 16 * 33;     // 2 x 4 x 32
    float* biasd = cst + 2 * 4 * 32;      // 16

    const int tid = threadIdx.x;
    const int grp = blockIdx.x >> 5;
    const int cta = blockIdx.x & 31;
    const int bg  = grp * 32;
    const int ub  = cta * 4;

    for (int idx = tid; idx < 16 * 128; idx += 256) {
        int row = idx >> 7, k = idx & 127;
        int grow = (row >> 2) * NHD + ub + (row & 3);
        wd0h[row * 132 + k] = dU0[grow * NHD + k];
        wd1i[row * 132 + k] = dW1[grow * NHD + k];
        wd1h[row * 132 + k] = dU1[grow * NHD + k];
    }
    if (tid < 16) {
        int grow = (tid >> 2) * NHD + ub + (tid & 3);
        biasd[tid] = db1[grow] + dc1[grow];
    }
    for (int idx = tid; idx < 512; idx += 256) {
        int b = idx >> 4, row = idx & 15;
        xw[b * 17 + row] = g_xwd0[(bg + b) * 4 * NHD + (row >> 2) * NHD + ub + (row & 3)];
    }
    for (int idx = tid; idx < 2 * 4 * 32; idx += 256) cst[idx] = 0.f;
    __syncthreads();

    for (int s = 0; s <= NT; s++) {
        {
            const float* h0g = g_hd0[(s + 1) & 1];
            const float* h1g = g_hd1[s & 1];
            for (int idx = tid; idx < 32 * 32; idx += 256) {
                int row = idx >> 5, c4 = (idx & 31) << 2;
                *(float4*)&hd0p[row * 132 + c4] = ldcg4(&h0g[(bg + row) * NHD + c4]);
                *(float4*)&hd1p[row * 132 + c4] = ldcg4(&h1g[(bg + row) * NHD + c4]);
            }
        }
        __syncthreads();

        if ((tid >> 5) < 4) {                       // layer 0, step s
            if (s < NT) {
                const int bs = tid & 7, row = tid >> 3;   // 0..15
                ull acc[4][2] = {};
#pragma unroll 4
                for (int k = 0; k < NHD; k += 4) {
                    ulonglong2 w = *(const ulonglong2*)&wd0h[row * 132 + k];
#pragma unroll
                    for (int i = 0; i < 4; i++) {
                        ulonglong2 a = *(const ulonglong2*)&hd0p[(bs + 8 * i) * 132 + k];
                        fma2(acc[i][0], a.x, w.x); fma2(acc[i][1], a.y, w.y);
                    }
                }
#pragma unroll
                for (int i = 0; i < 4; i++) {
                    int b = bs + 8 * i;
                    pre[row * 33 + b] = hadd2(acc[i][0]) + hadd2(acc[i][1]) + xw[b * 17 + row];
                }
            }
        } else {                                    // layer 1, step s-1
            if (s >= 1) {
                const int tl = tid - 128;
                const int bs = tl & 7, row = tl >> 3;
                ull acc[4][2] = {};
#pragma unroll 4
                for (int k = 0; k < NHD; k += 4) {
                    ulonglong2 w = *(const ulonglong2*)&wd1i[row * 132 + k];
#pragma unroll
                    for (int i = 0; i < 4; i++) {
                        ulonglong2 a = *(const ulonglong2*)&hd0p[(bs + 8 * i) * 132 + k];
                        fma2(acc[i][0], a.x, w.x); fma2(acc[i][1], a.y, w.y);
                    }
                }
#pragma unroll 4
                for (int k = 0; k < NHD; k += 4) {
                    ulonglong2 w = *(const ulonglong2*)&wd1h[row * 132 + k];
#pragma unroll
                    for (int i = 0; i < 4; i++) {
                        ulonglong2 a = *(const ulonglong2*)&hd1p[(bs + 8 * i) * 132 + k];
                        fma2(acc[i][0], a.x, w.x); fma2(acc[i][1], a.y, w.y);
                    }
                }
#pragma unroll
                for (int i = 0; i < 4; i++) {
                    int b = bs + 8 * i;
                    pre[528 + row * 33 + b] = hadd2(acc[i][0]) + hadd2(acc[i][1]) + biasd[row];
                }
            }
        }
        __syncthreads();

        {
            int layer = tid >> 7, q = tid & 127;
            int u = (q >> 5) & 3, b = q & 31;
            bool ok = (layer == 0) ? (s < NT) : (s >= 1);
            if (ok) {
                float gi = pre[layer * 528 + (0 * 4 + u) * 33 + b];
                float gf = pre[layer * 528 + (1 * 4 + u) * 33 + b];
                float gg = pre[layer * 528 + (2 * 4 + u) * 33 + b];
                float go = pre[layer * 528 + (3 * 4 + u) * 33 + b];
                float c  = cst[layer * 128 + u * 32 + b];
                float cv = sigf(gf) * c + sigf(gi) * tanhf(gg);
                cst[layer * 128 + u * 32 + b] = cv;
                float hv = sigf(go) * tanhf(cv);
                int gidx = (bg + b) * NHD + ub + u;
                if (layer == 0) g_hd0[s & 1][gidx] = hv;
                else {
                    g_hd1[(s - 1) & 1][gidx] = hv;
                    out[((bg + b) * NT + (s - 1)) * ND + ub + u] = hv;
                }
            }
        }
        group_barrier(&g_dbar[grp], 32u * (unsigned)(s + 1));
    }
}

extern "C" void kernel_launch(void* const* d_in, const int* in_sizes, int n_in,
                              void* d_out, int out_size)
{
    (void)in_sizes; (void)n_in; (void)out_size;
    const float* x   = (const float*)d_in[0];
    const float* eW0 = (const float*)d_in[1];
    const float* eU0 = (const float*)d_in[2];
    const float* eb0 = (const float*)d_in[3];
    const float* ec0 = (const float*)d_in[4];
    const float* eW1 = (const float*)d_in[5];
    const float* eU1 = (const float*)d_in[6];
    const float* eb1 = (const float*)d_in[7];
    const float* ec1 = (const float*)d_in[8];
    const float* dW0 = (const float*)d_in[9];
    const float* dU0 = (const float*)d_in[10];
    const float* db0 = (const float*)d_in[11];
    const float* dc0 = (const float*)d_in[12];
    const float* dW1 = (const float*)d_in[13];
    const float* dU1 = (const float*)d_in[14];
    const float* db1 = (const float*)d_in[15];
    const float* dc1 = (const float*)d_in[16];
    float* out = (float*)d_out;

    const int ENC_SMEM = (32*132 + 3*32*260 + 32*132 + 2*32*260 + 2*32*33 + 2*8*32 + 64) * 4;  // 210944
    const int DEC_SMEM = (3*16*132 + 2*32*132 + 32*17 + 2*16*33 + 2*4*32 + 16) * 4;            // 66624

    static bool attr_done = false;
    if (!attr_done) {
        cudaFuncSetAttribute(enc_persist, cudaFuncAttributeMaxDynamicSharedMemorySize, ENC_SMEM);
        cudaFuncSetAttribute(dec_persist, cudaFuncAttributeMaxDynamicSharedMemorySize, DEC_SMEM);
        attr_done = true;
    }

    zero_state_kernel<<<256, 256>>>();
    enc_persist<<<128, 256, ENC_SMEM>>>(x, eW0, eU0, eb0, ec0, eW1, eU1, eb1, ec1);
    xwd0_kernel<<<128, 512>>>(dW0, db0, dc0);
    dec_persist<<<128, 256, DEC_SMEM>>>(dU0, dW1, dU1, db1, dc1, out);
}

// round 8
// speedup vs baseline: 1.3037x; 1.3037x over previous
#include <cuda_runtime.h>

static constexpr int NB = 128, NT = 1024, ND = 128, NH = 256, NHD = 128;
typedef unsigned long long ull;

// global persistent state
__device__ __align__(16) float g_h0[2][NB * NH];
__device__ __align__(16) float g_h1[2][NB * NH];
__device__ __align__(16) float g_hd0[2][NB * NHD];
__device__ __align__(16) float g_hd1[2][NB * NHD];
__device__ __align__(16) float g_xwd0[NB * 4 * NHD];
__device__ unsigned g_ebar[128];   // one counter per 32 entries (128B apart)
__device__ unsigned g_dbar[128];

__device__ __forceinline__ void fma2(ull &acc, ull a, ull b) {
    asm("fma.rn.f32x2 %0, %1, %2, %0;" : "+l"(acc) : "l"(a), "l"(b));
}
__device__ __forceinline__ float hadd2(ull v) {
    float lo, hi;
    asm("mov.b64 {%0, %1}, %2;" : "=f"(lo), "=f"(hi) : "l"(v));
    return lo + hi;
}
__device__ __forceinline__ float sigf(float z) { return 1.0f / (1.0f + __expf(-z)); }
__device__ __forceinline__ float4 ldcg4(const float* p) {
    float4 v;
    asm volatile("ld.global.cg.v4.f32 {%0,%1,%2,%3}, [%4];"
                 : "=f"(v.x), "=f"(v.y), "=f"(v.z), "=f"(v.w) : "l"(p));
    return v;
}
__device__ __forceinline__ void bar_arrive(unsigned* p) {
    asm volatile("red.release.gpu.global.add.u32 [%0], 1;" :: "l"(p) : "memory");
}
__device__ __forceinline__ unsigned ld_acq(const unsigned* p) {
    unsigned v;
    asm volatile("ld.acquire.gpu.global.u32 %0, [%1];" : "=r"(v) : "l"(p) : "memory");
    return v;
}

__global__ void zero_state_kernel() {
    int i = blockIdx.x * blockDim.x + threadIdx.x;   // 65536 threads
    ((float*)g_h0)[i] = 0.f;
    ((float*)g_h1)[i] = 0.f;
    if (i < 2 * NB * NHD) { ((float*)g_hd0)[i] = 0.f; ((float*)g_hd1)[i] = 0.f; }
    if (i < 128) g_ebar[i] = 0u;
    else if (i < 256) g_dbar[i - 128] = 0u;
}

// =================== persistent encoder ===================
// 128 CTAs = 4 groups x 32 CTAs; group owns 32 batch rows; CTA owns 8 units
// of both layers (rows = gate*8+unit). 512 threads: 256 per layer, split-K=2.
__global__ void __launch_bounds__(512, 1) enc_persist(
    const float* __restrict__ x,
    const float* __restrict__ eW0, const float* __restrict__ eU0,
    const float* __restrict__ eb0, const float* __restrict__ ec0,
    const float* __restrict__ eW1, const float* __restrict__ eU1,
    const float* __restrict__ eb1, const float* __restrict__ ec1)
{
    extern __shared__ float sm[];
    float* w0x  = sm;                    // 32 x 132
    float* w0h  = w0x + 32 * 132;        // 32 x 260
    float* w1i  = w0h + 32 * 260;
    float* w1h  = w1i + 32 * 260;
    float* xs   = w1h + 32 * 260;        // 32 x 132
    float* h0p  = xs  + 32 * 132;        // 32 x 260
    float* h1p  = h0p + 32 * 260;
    float* pre  = h1p + 32 * 260;        // [kh2][L2][32][33]
    float* cst  = pre + 2 * 2 * 32 * 33; // [L2][b32*8+u]
    float* bias = cst + 2 * 256;         // 64

    const int tid = threadIdx.x;
    const int grp = blockIdx.x >> 5;
    const int cta = blockIdx.x & 31;
    const int bg  = grp * 32;
    const int ub  = cta * 8;
    unsigned* ebar = &g_ebar[grp * 32];

    // ---- load weights ----
    for (int idx = tid; idx < 32 * 128; idx += 512) {
        int row = idx >> 7, k = idx & 127;
        int grow = (row >> 3) * NH + ub + (row & 7);
        w0x[row * 132 + k] = eW0[grow * ND + k];
    }
    for (int idx = tid; idx < 32 * 256; idx += 512) {
        int row = idx >> 8, k = idx & 255;
        int grow = (row >> 3) * NH + ub + (row & 7);
        w0h[row * 260 + k] = eU0[grow * NH + k];
        w1i[row * 260 + k] = eW1[grow * NH + k];
        w1h[row * 260 + k] = eU1[grow * NH + k];
    }
    if (tid < 32) {
        int grow = (tid >> 3) * NH + ub + (tid & 7);
        bias[tid]      = eb0[grow] + ec0[grow];
        bias[32 + tid] = eb1[grow] + ec1[grow];
    }
    for (int idx = tid; idx < 2 * 256; idx += 512) cst[idx] = 0.f;

    // ---- prologue staging (s = 0): x and zeroed h ----
    for (int idx = tid; idx < 32 * 32; idx += 512) {
        int row = idx >> 5, c4 = (idx & 31) << 2;
        *(float4*)&xs[row * 132 + c4] =
            __ldg((const float4*)&x[((bg + row) * NT + 0) * ND + c4]);
    }
    {
        const float* h0g = g_h0[1];
        const float* h1g = g_h1[0];
        for (int idx = tid; idx < 32 * 64; idx += 512) {
            int row = idx >> 6, c4 = (idx & 63) << 2;
            *(float4*)&h0p[row * 260 + c4] = ldcg4(&h0g[(bg + row) * NH + c4]);
            *(float4*)&h1p[row * 260 + c4] = ldcg4(&h1g[(bg + row) * NH + c4]);
        }
    }
    __syncthreads();

    for (int s = 0; s <= NT; s++) {
        // ---- compute gate partial pre-activations ----
        if (tid < 256) {                 // layer 0, step s
            if (s < NT) {
                const int kh = tid >> 7, t = tid & 127;
                const int bs = t & 7, rp = t >> 3;
                const int r0 = 2 * rp, r1 = r0 + 1;
                ull acc[2][4][2] = {};
                if (kh == 0) {
#pragma unroll 2
                    for (int k = 0; k < ND; k += 4) {
                        ulonglong2 wa = *(const ulonglong2*)&w0x[r0 * 132 + k];
                        ulonglong2 wb = *(const ulonglong2*)&w0x[r1 * 132 + k];
#pragma unroll
                        for (int i = 0; i < 4; i++) {
                            ulonglong2 a = *(const ulonglong2*)&xs[(bs + 8 * i) * 132 + k];
                            fma2(acc[0][i][0], a.x, wa.x); fma2(acc[0][i][1], a.y, wa.y);
                            fma2(acc[1][i][0], a.x, wb.x); fma2(acc[1][i][1], a.y, wb.y);
                        }
                    }
#pragma unroll 2
                    for (int k = 0; k < 64; k += 4) {
                        ulonglong2 wa = *(const ulonglong2*)&w0h[r0 * 260 + k];
                        ulonglong2 wb = *(const ulonglong2*)&w0h[r1 * 260 + k];
#pragma unroll
                        for (int i = 0; i < 4; i++) {
                            ulonglong2 a = *(const ulonglong2*)&h0p[(bs + 8 * i) * 260 + k];
                            fma2(acc[0][i][0], a.x, wa.x); fma2(acc[0][i][1], a.y, wa.y);
                            fma2(acc[1][i][0], a.x, wb.x); fma2(acc[1][i][1], a.y, wb.y);
                        }
                    }
                } else {
#pragma unroll 2
                    for (int k = 64; k < NH; k += 4) {
                        ulonglong2 wa = *(const ulonglong2*)&w0h[r0 * 260 + k];
                        ulonglong2 wb = *(const ulonglong2*)&w0h[r1 * 260 + k];
#pragma unroll
                        for (int i = 0; i < 4; i++) {
                            ulonglong2 a = *(const ulonglong2*)&h0p[(bs + 8 * i) * 260 + k];
                            fma2(acc[0][i][0], a.x, wa.x); fma2(acc[0][i][1], a.y, wa.y);
                            fma2(acc[1][i][0], a.x, wb.x); fma2(acc[1][i][1], a.y, wb.y);
                        }
                    }
                }
                float ba = (kh == 0) ? bias[r0] : 0.f;
                float bb = (kh == 0) ? bias[r1] : 0.f;
                float* pb = pre + (kh * 2 + 0) * 1056;
#pragma unroll
                for (int i = 0; i < 4; i++) {
                    int b = bs + 8 * i;
                    pb[r0 * 33 + b] = hadd2(acc[0][i][0]) + hadd2(acc[0][i][1]) + ba;
                    pb[r1 * 33 + b] = hadd2(acc[1][i][0]) + hadd2(acc[1][i][1]) + bb;
                }
            }
        } else {                          // layer 1, step s-1
            if (s >= 1) {
                const int tl = tid - 256;
                const int kh = tl >> 7, t = tl & 127;
                const int bs = t & 7, rp = t >> 3;
                const int r0 = 2 * rp, r1 = r0 + 1;
                const float* wsel = (kh == 0) ? w1i : w1h;
                const float* asel = (kh == 0) ? h0p : h1p;
                ull acc[2][4][2] = {};
#pragma unroll 2
                for (int k = 0; k < NH; k += 4) {
                    ulonglong2 wa = *(const ulonglong2*)&wsel[r0 * 260 + k];
                    ulonglong2 wb = *(const ulonglong2*)&wsel[r1 * 260 + k];
#pragma unroll
                    for (int i = 0; i < 4; i++) {
                        ulonglong2 a = *(const ulonglong2*)&asel[(bs + 8 * i) * 260 + k];
                        fma2(acc[0][i][0], a.x, wa.x); fma2(acc[0][i][1], a.y, wa.y);
                        fma2(acc[1][i][0], a.x, wb.x); fma2(acc[1][i][1], a.y, wb.y);
                    }
                }
                float ba = (kh == 0) ? bias[32 + r0] : 0.f;
                float bb = (kh == 0) ? bias[32 + r1] : 0.f;
                float* pb = pre + (kh * 2 + 1) * 1056;
#pragma unroll
                for (int i = 0; i < 4; i++) {
                    int b = bs + 8 * i;
                    pb[r0 * 33 + b] = hadd2(acc[0][i][0]) + hadd2(acc[0][i][1]) + ba;
                    pb[r1 * 33 + b] = hadd2(acc[1][i][0]) + hadd2(acc[1][i][1]) + bb;
                }
            }
        }
        __syncthreads();

        // ---- combine halves + state update (coalesced h writes) ----
        {
            const int L = tid >> 8, u = tid & 7, b = (tid >> 3) & 31;
            bool ok = (L == 0) ? (s < NT) : (s >= 1);
            if (ok) {
                const float* pa = pre + L * 1056;         // kh = 0
                const float* pc = pre + (2 + L) * 1056;   // kh = 1
                float gi = pa[(0 * 8 + u) * 33 + b] + pc[(0 * 8 + u) * 33 + b];
                float gf = pa[(1 * 8 + u) * 33 + b] + pc[(1 * 8 + u) * 33 + b];
                float gg = pa[(2 * 8 + u) * 33 + b] + pc[(2 * 8 + u) * 33 + b];
                float go = pa[(3 * 8 + u) * 33 + b] + pc[(3 * 8 + u) * 33 + b];
                float c  = cst[L * 256 + b * 8 + u];
                float cv = sigf(gf) * c + sigf(gi) * tanhf(gg);
                cst[L * 256 + b * 8 + u] = cv;
                float hv = sigf(go) * tanhf(cv);
                int gidx = (bg + b) * NH + ub + u;
                if (L == 0) g_h0[s & 1][gidx] = hv;
                else        g_h1[(s - 1) & 1][gidx] = hv;
            }
        }
        __syncthreads();
        if (s == NT) break;

        // ---- arrive; overlap x staging; wait; stage h ----
        if (tid == 0) bar_arrive(ebar);
        if (s + 1 < NT) {
            for (int idx = tid; idx < 32 * 32; idx += 512) {
                int row = idx >> 5, c4 = (idx & 31) << 2;
                *(float4*)&xs[row * 132 + c4] =
                    __ldg((const float4*)&x[((bg + row) * NT + (s + 1)) * ND + c4]);
            }
        }
        if (tid == 0) {
            unsigned target = 32u * (unsigned)(s + 1);
            while (ld_acq(ebar) < target) { }
        }
        __syncthreads();
        {
            const float* h0g = g_h0[s & 1];           // h0 of step s
            const float* h1g = g_h1[(s + 1) & 1];     // h1 of step s-1
            for (int idx = tid; idx < 32 * 64; idx += 512) {
                int row = idx >> 6, c4 = (idx & 63) << 2;
                *(float4*)&h0p[row * 260 + c4] = ldcg4(&h0g[(bg + row) * NH + c4]);
                *(float4*)&h1p[row * 260 + c4] = ldcg4(&h1g[(bg + row) * NH + c4]);
            }
        }
        __syncthreads();
    }
}

// ---- decoder L0 constant input projection ----
__global__ void xwd0_kernel(const float* __restrict__ dW0,
                            const float* __restrict__ db0,
                            const float* __restrict__ dc0)
{
    int idx = blockIdx.x * blockDim.x + threadIdx.x;   // 65536
    int b = idx >> 9, gd = idx & 511;
    const float* hb = &g_h1[1][b * NH];                // h1[NT-1] in buffer 1
    const float* wr = dW0 + gd * NH;
    ull a0 = 0ULL, a1 = 0ULL;
#pragma unroll 4
    for (int k = 0; k < NH; k += 4) {
        ulonglong2 hv = *(const ulonglong2*)&hb[k];
        ulonglong2 wv = *(const ulonglong2*)&wr[k];
        fma2(a0, hv.x, wv.x); fma2(a1, hv.y, wv.y);
    }
    g_xwd0[idx] = hadd2(a0) + hadd2(a1) + db0[gd] + dc0[gd];
}

// =================== persistent decoder ===================
__global__ void __launch_bounds__(512, 1) dec_persist(
    const float* __restrict__ dU0,
    const float* __restrict__ dW1, const float* __restrict__ dU1,
    const float* __restrict__ db1, const float* __restrict__ dc1,
    float* __restrict__ out)
{
    extern __shared__ float sm[];
    float* wd0h  = sm;                    // 16 x 132
    float* wd1i  = wd0h + 16 * 132;
    float* wd1h  = wd1i + 16 * 132;
    float* hd0p  = wd1h + 16 * 132;       // 32 x 132
    float* hd1p  = hd0p + 32 * 132;
    float* xw    = hd1p + 32 * 132;       // 32 x 17
    float* pre   = xw + 32 * 17;          // [kh2][L2][16][33]
    float* cst   = pre + 2 * 2 * 16 * 33; // [L2][b32*4+u]
    float* biasd = cst + 2 * 128;         // 16

    const int tid = threadIdx.x;
    const int grp = blockIdx.x >> 5;
    const int cta = blockIdx.x & 31;
    const int bg  = grp * 32;
    const int ub  = cta * 4;
    unsigned* dbar = &g_dbar[grp * 32];

    for (int idx = tid; idx < 16 * 128; idx += 512) {
        int row = idx >> 7, k = idx & 127;
        int grow = (row >> 2) * NHD + ub + (row & 3);
        wd0h[row * 132 + k] = dU0[grow * NHD + k];
        wd1i[row * 132 + k] = dW1[grow * NHD + k];
        wd1h[row * 132 + k] = dU1[grow * NHD + k];
    }
    if (tid < 16) {
        int grow = (tid >> 2) * NHD + ub + (tid & 3);
        biasd[tid] = db1[grow] + dc1[grow];
    }
    for (int idx = tid; idx < 512; idx += 512) {
        int b = idx >> 4, row = idx & 15;
        xw[b * 17 + row] = g_xwd0[(bg + b) * 4 * NHD + (row >> 2) * NHD + ub + (row & 3)];
    }
    for (int idx = tid; idx < 2 * 128; idx += 512) cst[idx] = 0.f;
    {
        const float* h0g = g_hd0[1];
        const float* h1g = g_hd1[0];
        for (int idx = tid; idx < 32 * 32; idx += 512) {
            int row = idx >> 5, c4 = (idx & 31) << 2;
            *(float4*)&hd0p[row * 132 + c4] = ldcg4(&h0g[(bg + row) * NHD + c4]);
            *(float4*)&hd1p[row * 132 + c4] = ldcg4(&h1g[(bg + row) * NHD + c4]);
        }
    }
    __syncthreads();

    for (int s = 0; s <= NT; s++) {
        if (tid < 256) {                  // layer 0, step s
            if (s < NT) {
                const int kh = tid >> 7, t = tid & 127;
                const int bs = t & 15, rp = t >> 4;
                const int r0 = 2 * rp, r1 = r0 + 1;
                const int k0 = kh * 64, k1 = k0 + 64;
                ull acc[2][2][2] = {};
#pragma unroll 2
                for (int k = k0; k < k1; k += 4) {
                    ulonglong2 wa = *(const ulonglong2*)&wd0h[r0 * 132 + k];
                    ulonglong2 wb = *(const ulonglong2*)&wd0h[r1 * 132 + k];
#pragma unroll
                    for (int i = 0; i < 2; i++) {
                        ulonglong2 a = *(const ulonglong2*)&hd0p[(bs + 16 * i) * 132 + k];
                        fma2(acc[0][i][0], a.x, wa.x); fma2(acc[0][i][1], a.y, wa.y);
                        fma2(acc[1][i][0], a.x, wb.x); fma2(acc[1][i][1], a.y, wb.y);
                    }
                }
                float* pb = pre + (kh * 2 + 0) * 528;
#pragma unroll
                for (int i = 0; i < 2; i++) {
                    int b = bs + 16 * i;
                    float xa = (kh == 0) ? xw[b * 17 + r0] : 0.f;
                    float xb = (kh == 0) ? xw[b * 17 + r1] : 0.f;
                    pb[r0 * 33 + b] = hadd2(acc[0][i][0]) + hadd2(acc[0][i][1]) + xa;
                    pb[r1 * 33 + b] = hadd2(acc[1][i][0]) + hadd2(acc[1][i][1]) + xb;
                }
            }
        } else {                          // layer 1, step s-1
            if (s >= 1) {
                const int tl = tid - 256;
                const int kh = tl >> 7, t = tl & 127;
                const int bs = t & 15, rp = t >> 4;
                const int r0 = 2 * rp, r1 = r0 + 1;
                const float* wsel = (kh == 0) ? wd1i : wd1h;
                const float* asel = (kh == 0) ? hd0p : hd1p;
                ull acc[2][2][2] = {};
#pragma unroll 2
                for (int k = 0; k < NHD; k += 4) {
                    ulonglong2 wa = *(const ulonglong2*)&wsel[r0 * 132 + k];
                    ulonglong2 wb = *(const ulonglong2*)&wsel[r1 * 132 + k];
#pragma unroll
                    for (int i = 0; i < 2; i++) {
                        ulonglong2 a = *(const ulonglong2*)&asel[(bs + 16 * i) * 132 + k];
                        fma2(acc[0][i][0], a.x, wa.x); fma2(acc[0][i][1], a.y, wa.y);
                        fma2(acc[1][i][0], a.x, wb.x); fma2(acc[1][i][1], a.y, wb.y);
                    }
                }
                float ba = (kh == 0) ? biasd[r0] : 0.f;
                float bb = (kh == 0) ? biasd[r1] : 0.f;
                float* pb = pre + (kh * 2 + 1) * 528;
#pragma unroll
                for (int i = 0; i < 2; i++) {
                    int b = bs + 16 * i;
                    pb[r0 * 33 + b] = hadd2(acc[0][i][0]) + hadd2(acc[0][i][1]) + ba;
                    pb[r1 * 33 + b] = hadd2(acc[1][i][0]) + hadd2(acc[1][i][1]) + bb;
                }
            }
        }
        __syncthreads();

        if (tid < 256) {
            const int L = tid >> 7, q = tid & 127;
            const int u = q & 3, b = (q >> 2) & 31;
            bool ok = (L == 0) ? (s < NT) : (s >= 1);
            if (ok) {
                const float* pa = pre + L * 528;
                const float* pc = pre + (2 + L) * 528;
                float gi = pa[(0 * 4 + u) * 33 + b] + pc[(0 * 4 + u) * 33 + b];
                float gf = pa[(1 * 4 + u) * 33 + b] + pc[(1 * 4 + u) * 33 + b];
                float gg = pa[(2 * 4 + u) * 33 + b] + pc[(2 * 4 + u) * 33 + b];
                float go = pa[(3 * 4 + u) * 33 + b] + pc[(3 * 4 + u) * 33 + b];
                float c  = cst[L * 128 + b * 4 + u];
                float cv = sigf(gf) * c + sigf(gi) * tanhf(gg);
                cst[L * 128 + b * 4 + u] = cv;
                float hv = sigf(go) * tanhf(cv);
                int gidx = (bg + b) * NHD + ub + u;
                if (L == 0) g_hd0[s & 1][gidx] = hv;
                else {
                    g_hd1[(s - 1) & 1][gidx] = hv;
                    out[((bg + b) * NT + (s - 1)) * ND + ub + u] = hv;
                }
            }
        }
        __syncthreads();
        if (s == NT) break;

        if (tid == 0) {
            bar_arrive(dbar);
            unsigned target = 32u * (unsigned)(s + 1);
            while (ld_acq(dbar) < target) { }
        }
        __syncthreads();
        {
            const float* h0g = g_hd0[s & 1];
            const float* h1g = g_hd1[(s + 1) & 1];
            for (int idx = tid; idx < 32 * 32; idx += 512) {
                int row = idx >> 5, c4 = (idx & 31) << 2;
                *(float4*)&hd0p[row * 132 + c4] = ldcg4(&h0g[(bg + row) * NHD + c4]);
                *(float4*)&hd1p[row * 132 + c4] = ldcg4(&h1g[(bg + row) * NHD + c4]);
            }
        }
        __syncthreads();
    }
}

extern "C" void kernel_launch(void* const* d_in, const int* in_sizes, int n_in,
                              void* d_out, int out_size)
{
    (void)in_sizes; (void)n_in; (void)out_size;
    const float* x   = (const float*)d_in[0];
    const float* eW0 = (const float*)d_in[1];
    const float* eU0 = (const float*)d_in[2];
    const float* eb0 = (const float*)d_in[3];
    const float* ec0 = (const float*)d_in[4];
    const float* eW1 = (const float*)d_in[5];
    const float* eU1 = (const float*)d_in[6];
    const float* eb1 = (const float*)d_in[7];
    const float* ec1 = (const float*)d_in[8];
    const float* dW0 = (const float*)d_in[9];
    const float* dU0 = (const float*)d_in[10];
    const float* db0 = (const float*)d_in[11];
    const float* dc0 = (const float*)d_in[12];
    const float* dW1 = (const float*)d_in[13];
    const float* dU1 = (const float*)d_in[14];
    const float* db1 = (const float*)d_in[15];
    const float* dc1 = (const float*)d_in[16];
    float* out = (float*)d_out;

    const int ENC_SMEM = 54848 * 4;   // 219392 B
    const int DEC_SMEM = 17712 * 4;   // 70848 B

    static bool attr_done = false;
    if (!attr_done) {
        cudaFuncSetAttribute(enc_persist, cudaFuncAttributeMaxDynamicSharedMemorySize, ENC_SMEM);
        cudaFuncSetAttribute(dec_persist, cudaFuncAttributeMaxDynamicSharedMemorySize, DEC_SMEM);
        attr_done = true;
    }

    zero_state_kernel<<<128, 512>>>();
    enc_persist<<<128, 512, ENC_SMEM>>>(x, eW0, eU0, eb0, ec0, eW1, eU1, eb1, ec1);
    xwd0_kernel<<<128, 512>>>(dW0, db0, dc0);
    dec_persist<<<128, 512, DEC_SMEM>>>(dU0, dW1, dU1, db1, dc1, out);
}

// round 9
// speedup vs baseline: 1.3127x; 1.0069x over previous
#include <cuda_runtime.h>

static constexpr int NB = 128, NT = 1024, ND = 128, NH = 256, NHD = 128;
typedef unsigned long long ull;

// global persistent state
__device__ __align__(16) float g_h0[2][NB * NH];
__device__ __align__(16) float g_h1[2][NB * NH];
__device__ __align__(16) float g_hd0[2][NB * NHD];
__device__ __align__(16) float g_hd1[2][NB * NHD];
__device__ __align__(16) float g_xwd0[NB * 4 * NHD];
__device__ unsigned g_ebar[128];   // one counter per 32 entries (128B apart)
__device__ unsigned g_dbar[128];

__device__ __forceinline__ void fma2(ull &acc, ull a, ull b) {
    asm("fma.rn.f32x2 %0, %1, %2, %0;" : "+l"(acc) : "l"(a), "l"(b));
}
__device__ __forceinline__ float hadd2(ull v) {
    float lo, hi;
    asm("mov.b64 {%0, %1}, %2;" : "=f"(lo), "=f"(hi) : "l"(v));
    return lo + hi;
}
__device__ __forceinline__ float sigf(float z) { return 1.0f / (1.0f + __expf(-z)); }
__device__ __forceinline__ float4 ldcg4(const float* p) {
    float4 v;
    asm volatile("ld.global.cg.v4.f32 {%0,%1,%2,%3}, [%4];"
                 : "=f"(v.x), "=f"(v.y), "=f"(v.z), "=f"(v.w) : "l"(p));
    return v;
}
__device__ __forceinline__ void bar_arrive(unsigned* p) {
    asm volatile("red.release.gpu.global.add.u32 [%0], 1;" :: "l"(p) : "memory");
}
__device__ __forceinline__ unsigned ld_acq(const unsigned* p) {
    unsigned v;
    asm volatile("ld.acquire.gpu.global.u32 %0, [%1];" : "=r"(v) : "l"(p) : "memory");
    return v;
}

__global__ void zero_state_kernel() {
    int i = blockIdx.x * blockDim.x + threadIdx.x;   // 65536 threads
    ((float*)g_h0)[i] = 0.f;
    ((float*)g_h1)[i] = 0.f;
    if (i < 2 * NB * NHD) { ((float*)g_hd0)[i] = 0.f; ((float*)g_hd1)[i] = 0.f; }
    if (i < 128) g_ebar[i] = 0u;
    else if (i < 256) g_dbar[i - 128] = 0u;
}

// =================== persistent encoder ===================
// 128 CTAs = 4 groups x 32 CTAs; group owns 32 batch rows; CTA owns 8 units
// of both layers (rows = gate*8+unit). 512 threads: 256 per layer, split-K=2.
__global__ void __launch_bounds__(512, 1) enc_persist(
    const float* __restrict__ x,
    const float* __restrict__ eW0, const float* __restrict__ eU0,
    const float* __restrict__ eb0, const float* __restrict__ ec0,
    const float* __restrict__ eW1, const float* __restrict__ eU1,
    const float* __restrict__ eb1, const float* __restrict__ ec1)
{
    extern __shared__ float sm[];
    float* w0x  = sm;                    // 32 x 132
    float* w0h  = w0x + 32 * 132;        // 32 x 260
    float* w1i  = w0h + 32 * 260;
    float* w1h  = w1i + 32 * 260;
    float* xs   = w1h + 32 * 260;        // 32 x 132
    float* h0p  = xs  + 32 * 132;        // 32 x 260
    float* h1p  = h0p + 32 * 260;
    float* pre  = h1p + 32 * 260;        // [kh2][L2][32][33]
    float* cst  = pre + 2 * 2 * 32 * 33; // [L2][b32*8+u]
    float* bias = cst + 2 * 256;         // 64

    const int tid = threadIdx.x;
    const int grp = blockIdx.x >> 5;
    const int cta = blockIdx.x & 31;
    const int bg  = grp * 32;
    const int ub  = cta * 8;
    unsigned* ebar = &g_ebar[grp * 32];

    // ---- load weights ----
    for (int idx = tid; idx < 32 * 128; idx += 512) {
        int row = idx >> 7, k = idx & 127;
        int grow = (row >> 3) * NH + ub + (row & 7);
        w0x[row * 132 + k] = eW0[grow * ND + k];
    }
    for (int idx = tid; idx < 32 * 256; idx += 512) {
        int row = idx >> 8, k = idx & 255;
        int grow = (row >> 3) * NH + ub + (row & 7);
        w0h[row * 260 + k] = eU0[grow * NH + k];
        w1i[row * 260 + k] = eW1[grow * NH + k];
        w1h[row * 260 + k] = eU1[grow * NH + k];
    }
    if (tid < 32) {
        int grow = (tid >> 3) * NH + ub + (tid & 7);
        bias[tid]      = eb0[grow] + ec0[grow];
        bias[32 + tid] = eb1[grow] + ec1[grow];
    }
    for (int idx = tid; idx < 2 * 256; idx += 512) cst[idx] = 0.f;

    // ---- prologue staging (s = 0): x and zeroed h ----
    for (int idx = tid; idx < 32 * 32; idx += 512) {
        int row = idx >> 5, c4 = (idx & 31) << 2;
        *(float4*)&xs[row * 132 + c4] =
            __ldg((const float4*)&x[((bg + row) * NT + 0) * ND + c4]);
    }
    {
        const float* h0g = g_h0[1];
        const float* h1g = g_h1[0];
        for (int idx = tid; idx < 32 * 64; idx += 512) {
            int row = idx >> 6, c4 = (idx & 63) << 2;
            *(float4*)&h0p[row * 260 + c4] = ldcg4(&h0g[(bg + row) * NH + c4]);
            *(float4*)&h1p[row * 260 + c4] = ldcg4(&h1g[(bg + row) * NH + c4]);
        }
    }
    __syncthreads();

    for (int s = 0; s <= NT; s++) {
        // ---- compute gate partial pre-activations ----
        if (tid < 256) {                 // layer 0, step s
            if (s < NT) {
                const int kh = tid >> 7, t = tid & 127;
                const int bs = t & 7, rp = t >> 3;
                const int r0 = 2 * rp, r1 = r0 + 1;
                ull acc[2][4][2] = {};
                if (kh == 0) {
#pragma unroll 2
                    for (int k = 0; k < ND; k += 4) {
                        ulonglong2 wa = *(const ulonglong2*)&w0x[r0 * 132 + k];
                        ulonglong2 wb = *(const ulonglong2*)&w0x[r1 * 132 + k];
#pragma unroll
                        for (int i = 0; i < 4; i++) {
                            ulonglong2 a = *(const ulonglong2*)&xs[(bs + 8 * i) * 132 + k];
                            fma2(acc[0][i][0], a.x, wa.x); fma2(acc[0][i][1], a.y, wa.y);
                            fma2(acc[1][i][0], a.x, wb.x); fma2(acc[1][i][1], a.y, wb.y);
                        }
                    }
#pragma unroll 2
                    for (int k = 0; k < 64; k += 4) {
                        ulonglong2 wa = *(const ulonglong2*)&w0h[r0 * 260 + k];
                        ulonglong2 wb = *(const ulonglong2*)&w0h[r1 * 260 + k];
#pragma unroll
                        for (int i = 0; i < 4; i++) {
                            ulonglong2 a = *(const ulonglong2*)&h0p[(bs + 8 * i) * 260 + k];
                            fma2(acc[0][i][0], a.x, wa.x); fma2(acc[0][i][1], a.y, wa.y);
                            fma2(acc[1][i][0], a.x, wb.x); fma2(acc[1][i][1], a.y, wb.y);
                        }
                    }
                } else {
#pragma unroll 2
                    for (int k = 64; k < NH; k += 4) {
                        ulonglong2 wa = *(const ulonglong2*)&w0h[r0 * 260 + k];
                        ulonglong2 wb = *(const ulonglong2*)&w0h[r1 * 260 + k];
#pragma unroll
                        for (int i = 0; i < 4; i++) {
                            ulonglong2 a = *(const ulonglong2*)&h0p[(bs + 8 * i) * 260 + k];
                            fma2(acc[0][i][0], a.x, wa.x); fma2(acc[0][i][1], a.y, wa.y);
                            fma2(acc[1][i][0], a.x, wb.x); fma2(acc[1][i][1], a.y, wb.y);
                        }
                    }
                }
                float ba = (kh == 0) ? bias[r0] : 0.f;
                float bb = (kh == 0) ? bias[r1] : 0.f;
                float* pb = pre + (kh * 2 + 0) * 1056;
#pragma unroll
                for (int i = 0; i < 4; i++) {
                    int b = bs + 8 * i;
                    pb[r0 * 33 + b] = hadd2(acc[0][i][0]) + hadd2(acc[0][i][1]) + ba;
                    pb[r1 * 33 + b] = hadd2(acc[1][i][0]) + hadd2(acc[1][i][1]) + bb;
                }
            }
        } else {                          // layer 1, step s-1
            if (s >= 1) {
                const int tl = tid - 256;
                const int kh = tl >> 7, t = tl & 127;
                const int bs = t & 7, rp = t >> 3;
                const int r0 = 2 * rp, r1 = r0 + 1;
                const float* wsel = (kh == 0) ? w1i : w1h;
                const float* asel = (kh == 0) ? h0p : h1p;
                ull acc[2][4][2] = {};
#pragma unroll 2
                for (int k = 0; k < NH; k += 4) {
                    ulonglong2 wa = *(const ulonglong2*)&wsel[r0 * 260 + k];
                    ulonglong2 wb = *(const ulonglong2*)&wsel[r1 * 260 + k];
#pragma unroll
                    for (int i = 0; i < 4; i++) {
                        ulonglong2 a = *(const ulonglong2*)&asel[(bs + 8 * i) * 260 + k];
                        fma2(acc[0][i][0], a.x, wa.x); fma2(acc[0][i][1], a.y, wa.y);
                        fma2(acc[1][i][0], a.x, wb.x); fma2(acc[1][i][1], a.y, wb.y);
                    }
                }
                float ba = (kh == 0) ? bias[32 + r0] : 0.f;
                float bb = (kh == 0) ? bias[32 + r1] : 0.f;
                float* pb = pre + (kh * 2 + 1) * 1056;
#pragma unroll
                for (int i = 0; i < 4; i++) {
                    int b = bs + 8 * i;
                    pb[r0 * 33 + b] = hadd2(acc[0][i][0]) + hadd2(acc[0][i][1]) + ba;
                    pb[r1 * 33 + b] = hadd2(acc[1][i][0]) + hadd2(acc[1][i][1]) + bb;
                }
            }
        }
        __syncthreads();

        // ---- combine halves + state update (coalesced h writes) ----
        {
            const int L = tid >> 8, u = tid & 7, b = (tid >> 3) & 31;
            bool ok = (L == 0) ? (s < NT) : (s >= 1);
            if (ok) {
                const float* pa = pre + L * 1056;         // kh = 0
                const float* pc = pre + (2 + L) * 1056;   // kh = 1
                float gi = pa[(0 * 8 + u) * 33 + b] + pc[(0 * 8 + u) * 33 + b];
                float gf = pa[(1 * 8 + u) * 33 + b] + pc[(1 * 8 + u) * 33 + b];
                float gg = pa[(2 * 8 + u) * 33 + b] + pc[(2 * 8 + u) * 33 + b];
                float go = pa[(3 * 8 + u) * 33 + b] + pc[(3 * 8 + u) * 33 + b];
                float c  = cst[L * 256 + b * 8 + u];
                float cv = sigf(gf) * c + sigf(gi) * tanhf(gg);
                cst[L * 256 + b * 8 + u] = cv;
                float hv = sigf(go) * tanhf(cv);
                int gidx = (bg + b) * NH + ub + u;
                if (L == 0) g_h0[s & 1][gidx] = hv;
                else        g_h1[(s - 1) & 1][gidx] = hv;
            }
        }
        __syncthreads();
        if (s == NT) break;

        // ---- arrive; overlap x staging; wait; stage h ----
        if (tid == 0) bar_arrive(ebar);
        if (s + 1 < NT) {
            for (int idx = tid; idx < 32 * 32; idx += 512) {
                int row = idx >> 5, c4 = (idx & 31) << 2;
                *(float4*)&xs[row * 132 + c4] =
                    __ldg((const float4*)&x[((bg + row) * NT + (s + 1)) * ND + c4]);
            }
        }
        if (tid == 0) {
            unsigned target = 32u * (unsigned)(s + 1);
            while (ld_acq(ebar) < target) { }
        }
        __syncthreads();
        {
            const float* h0g = g_h0[s & 1];           // h0 of step s
            const float* h1g = g_h1[(s + 1) & 1];     // h1 of step s-1
            for (int idx = tid; idx < 32 * 64; idx += 512) {
                int row = idx >> 6, c4 = (idx & 63) << 2;
                *(float4*)&h0p[row * 260 + c4] = ldcg4(&h0g[(bg + row) * NH + c4]);
                *(float4*)&h1p[row * 260 + c4] = ldcg4(&h1g[(bg + row) * NH + c4]);
            }
        }
        __syncthreads();
    }
}

// ---- decoder L0 constant input projection ----
__global__ void xwd0_kernel(const float* __restrict__ dW0,
                            const float* __restrict__ db0,
                            const float* __restrict__ dc0)
{
    int idx = blockIdx.x * blockDim.x + threadIdx.x;   // 65536
    int b = idx >> 9, gd = idx & 511;
    const float* hb = &g_h1[1][b * NH];                // h1[NT-1] in buffer 1
    const float* wr = dW0 + gd * NH;
    ull a0 = 0ULL, a1 = 0ULL;
#pragma unroll 4
    for (int k = 0; k < NH; k += 4) {
        ulonglong2 hv = *(const ulonglong2*)&hb[k];
        ulonglong2 wv = *(const ulonglong2*)&wr[k];
        fma2(a0, hv.x, wv.x); fma2(a1, hv.y, wv.y);
    }
    g_xwd0[idx] = hadd2(a0) + hadd2(a1) + db0[gd] + dc0[gd];
}

// =================== persistent decoder ===================
__global__ void __launch_bounds__(512, 1) dec_persist(
    const float* __restrict__ dU0,
    const float* __restrict__ dW1, const float* __restrict__ dU1,
    const float* __restrict__ db1, const float* __restrict__ dc1,
    float* __restrict__ out)
{
    extern __shared__ float sm[];
    float* wd0h  = sm;                    // 16 x 132
    float* wd1i  = wd0h + 16 * 132;
    float* wd1h  = wd1i + 16 * 132;
    float* hd0p  = wd1h + 16 * 132;       // 32 x 132
    float* hd1p  = hd0p + 32 * 132;
    float* xw    = hd1p + 32 * 132;       // 32 x 17
    float* pre   = xw + 32 * 17;          // [kh2][L2][16][33]
    float* cst   = pre + 2 * 2 * 16 * 33; // [L2][b32*4+u]
    float* biasd = cst + 2 * 128;         // 16

    const int tid = threadIdx.x;
    const int grp = blockIdx.x >> 5;
    const int cta = blockIdx.x & 31;
    const int bg  = grp * 32;
    const int ub  = cta * 4;
    unsigned* dbar = &g_dbar[grp * 32];

    for (int idx = tid; idx < 16 * 128; idx += 512) {
        int row = idx >> 7, k = idx & 127;
        int grow = (row >> 2) * NHD + ub + (row & 3);
        wd0h[row * 132 + k] = dU0[grow * NHD + k];
        wd1i[row * 132 + k] = dW1[grow * NHD + k];
        wd1h[row * 132 + k] = dU1[grow * NHD + k];
    }
    if (tid < 16) {
        int grow = (tid >> 2) * NHD + ub + (tid & 3);
        biasd[tid] = db1[grow] + dc1[grow];
    }
    for (int idx = tid; idx < 512; idx += 512) {
        int b = idx >> 4, row = idx & 15;
        xw[b * 17 + row] = g_xwd0[(bg + b) * 4 * NHD + (row >> 2) * NHD + ub + (row & 3)];
    }
    for (int idx = tid; idx < 2 * 128; idx += 512) cst[idx] = 0.f;
    {
        const float* h0g = g_hd0[1];
        const float* h1g = g_hd1[0];
        for (int idx = tid; idx < 32 * 32; idx += 512) {
            int row = idx >> 5, c4 = (idx & 31) << 2;
            *(float4*)&hd0p[row * 132 + c4] = ldcg4(&h0g[(bg + row) * NHD + c4]);
            *(float4*)&hd1p[row * 132 + c4] = ldcg4(&h1g[(bg + row) * NHD + c4]);
        }
    }
    __syncthreads();

    for (int s = 0; s <= NT; s++) {
        if (tid < 256) {                  // layer 0, step s
            if (s < NT) {
                const int kh = tid >> 7, t = tid & 127;
                const int bs = t & 15, rp = t >> 4;
                const int r0 = 2 * rp, r1 = r0 + 1;
                const int k0 = kh * 64, k1 = k0 + 64;
                ull acc[2][2][2] = {};
#pragma unroll 2
                for (int k = k0; k < k1; k += 4) {
                    ulonglong2 wa = *(const ulonglong2*)&wd0h[r0 * 132 + k];
                    ulonglong2 wb = *(const ulonglong2*)&wd0h[r1 * 132 + k];
#pragma unroll
                    for (int i = 0; i < 2; i++) {
                        ulonglong2 a = *(const ulonglong2*)&hd0p[(bs + 16 * i) * 132 + k];
                        fma2(acc[0][i][0], a.x, wa.x); fma2(acc[0][i][1], a.y, wa.y);
                        fma2(acc[1][i][0], a.x, wb.x); fma2(acc[1][i][1], a.y, wb.y);
                    }
                }
                float* pb = pre + (kh * 2 + 0) * 528;
#pragma unroll
                for (int i = 0; i < 2; i++) {
                    int b = bs + 16 * i;
                    float xa = (kh == 0) ? xw[b * 17 + r0] : 0.f;
                    float xb = (kh == 0) ? xw[b * 17 + r1] : 0.f;
                    pb[r0 * 33 + b] = hadd2(acc[0][i][0]) + hadd2(acc[0][i][1]) + xa;
                    pb[r1 * 33 + b] = hadd2(acc[1][i][0]) + hadd2(acc[1][i][1]) + xb;
                }
            }
        } else {                          // layer 1, step s-1
            if (s >= 1) {
                const int tl = tid - 256;
                const int kh = tl >> 7, t = tl & 127;
                const int bs = t & 15, rp = t >> 4;
                const int r0 = 2 * rp, r1 = r0 + 1;
                const float* wsel = (kh == 0) ? wd1i : wd1h;
                const float* asel = (kh == 0) ? hd0p : hd1p;
                ull acc[2][2][2] = {};
#pragma unroll 2
                for (int k = 0; k < NHD; k += 4) {
                    ulonglong2 wa = *(const ulonglong2*)&wsel[r0 * 132 + k];
                    ulonglong2 wb = *(const ulonglong2*)&wsel[r1 * 132 + k];
#pragma unroll
                    for (int i = 0; i < 2; i++) {
                        ulonglong2 a = *(const ulonglong2*)&asel[(bs + 16 * i) * 132 + k];
                        fma2(acc[0][i][0], a.x, wa.x); fma2(acc[0][i][1], a.y, wa.y);
                        fma2(acc[1][i][0], a.x, wb.x); fma2(acc[1][i][1], a.y, wb.y);
                    }
                }
                float ba = (kh == 0) ? biasd[r0] : 0.f;
                float bb = (kh == 0) ? biasd[r1] : 0.f;
                float* pb = pre + (kh * 2 + 1) * 528;
#pragma unroll
                for (int i = 0; i < 2; i++) {
                    int b = bs + 16 * i;
                    pb[r0 * 33 + b] = hadd2(acc[0][i][0]) + hadd2(acc[0][i][1]) + ba;
                    pb[r1 * 33 + b] = hadd2(acc[1][i][0]) + hadd2(acc[1][i][1]) + bb;
                }
            }
        }
        __syncthreads();

        if (tid < 256) {
            const int L = tid >> 7, q = tid & 127;
            const int u = q & 3, b = (q >> 2) & 31;
            bool ok = (L == 0) ? (s < NT) : (s >= 1);
            if (ok) {
                const float* pa = pre + L * 528;
                const float* pc = pre + (2 + L) * 528;
                float gi = pa[(0 * 4 + u) * 33 + b] + pc[(0 * 4 + u) * 33 + b];
                float gf = pa[(1 * 4 + u) * 33 + b] + pc[(1 * 4 + u) * 33 + b];
                float gg = pa[(2 * 4 + u) * 33 + b] + pc[(2 * 4 + u) * 33 + b];
                float go = pa[(3 * 4 + u) * 33 + b] + pc[(3 * 4 + u) * 33 + b];
                float c  = cst[L * 128 + b * 4 + u];
                float cv = sigf(gf) * c + sigf(gi) * tanhf(gg);
                cst[L * 128 + b * 4 + u] = cv;
                float hv = sigf(go) * tanhf(cv);
                int gidx = (bg + b) * NHD + ub + u;
                if (L == 0) g_hd0[s & 1][gidx] = hv;
                else {
                    g_hd1[(s - 1) & 1][gidx] = hv;
                    out[((bg + b) * NT + (s - 1)) * ND + ub + u] = hv;
                }
            }
        }
        __syncthreads();
        if (s == NT) break;

        if (tid == 0) {
            bar_arrive(dbar);
            unsigned target = 32u * (unsigned)(s + 1);
            while (ld_acq(dbar) < target) { }
        }
        __syncthreads();
        {
            const float* h0g = g_hd0[s & 1];
            const float* h1g = g_hd1[(s + 1) & 1];
            for (int idx = tid; idx < 32 * 32; idx += 512) {
                int row = idx >> 5, c4 = (idx & 31) << 2;
                *(float4*)&hd0p[row * 132 + c4] = ldcg4(&h0g[(bg + row) * NHD + c4]);
                *(float4*)&hd1p[row * 132 + c4] = ldcg4(&h1g[(bg + row) * NHD + c4]);
            }
        }
        __syncthreads();
    }
}

extern "C" void kernel_launch(void* const* d_in, const int* in_sizes, int n_in,
                              void* d_out, int out_size)
{
    (void)in_sizes; (void)n_in; (void)out_size;
    const float* x   = (const float*)d_in[0];
    const float* eW0 = (const float*)d_in[1];
    const float* eU0 = (const float*)d_in[2];
    const float* eb0 = (const float*)d_in[3];
    const float* ec0 = (const float*)d_in[4];
    const float* eW1 = (const float*)d_in[5];
    const float* eU1 = (const float*)d_in[6];
    const float* eb1 = (const float*)d_in[7];
    const float* ec1 = (const float*)d_in[8];
    const float* dW0 = (const float*)d_in[9];
    const float* dU0 = (const float*)d_in[10];
    const float* db0 = (const float*)d_in[11];
    const float* dc0 = (const float*)d_in[12];
    const float* dW1 = (const float*)d_in[13];
    const float* dU1 = (const float*)d_in[14];
    const float* db1 = (const float*)d_in[15];
    const float* dc1 = (const float*)d_in[16];
    float* out = (float*)d_out;

    const int ENC_SMEM = 54848 * 4;   // 219392 B
    const int DEC_SMEM = 17712 * 4;   // 70848 B

    static bool attr_done = false;
    if (!attr_done) {
        cudaFuncSetAttribute(enc_persist, cudaFuncAttributeMaxDynamicSharedMemorySize, ENC_SMEM);
        cudaFuncSetAttribute(dec_persist, cudaFuncAttributeMaxDynamicSharedMemorySize, DEC_SMEM);
        attr_done = true;
    }

    zero_state_kernel<<<128, 512>>>();
    enc_persist<<<128, 512, ENC_SMEM>>>(x, eW0, eU0, eb0, ec0, eW1, eU1, eb1, ec1);
    xwd0_kernel<<<128, 512>>>(dW0, db0, dc0);
    dec_persist<<<128, 512, DEC_SMEM>>>(dU0, dW1, dU1, db1, dc1, out);
}

// round 10
// speedup vs baseline: 1.5517x; 1.1821x over previous
#include <cuda_runtime.h>

static constexpr int NB = 128, NT = 1024, ND = 128, NH = 256, NHD = 128;
typedef unsigned long long ull;

// global persistent state
__device__ __align__(16) float g_h0[2][NB * NH];
__device__ __align__(16) float g_h1[2][NB * NH];
__device__ __align__(16) float g_hd0[2][NB * NHD];
__device__ __align__(16) float g_hd1[2][NB * NHD];
__device__ __align__(16) float g_xwd0[NB * 4 * NHD];
__device__ unsigned g_ebar[128];   // one counter per 32 entries (128B apart)
__device__ unsigned g_dbar[128];

__device__ __forceinline__ void fma2(ull &acc, ull a, ull b) {
    asm("fma.rn.f32x2 %0, %1, %2, %0;" : "+l"(acc) : "l"(a), "l"(b));
}
__device__ __forceinline__ float hadd2(ull v) {
    float lo, hi;
    asm("mov.b64 {%0, %1}, %2;" : "=f"(lo), "=f"(hi) : "l"(v));
    return lo + hi;
}
__device__ __forceinline__ float sigf(float z) { return 1.0f / (1.0f + __expf(-z)); }
__device__ __forceinline__ float4 ldcg4(const float* p) {
    float4 v;
    asm volatile("ld.global.cg.v4.f32 {%0,%1,%2,%3}, [%4];"
                 : "=f"(v.x), "=f"(v.y), "=f"(v.z), "=f"(v.w) : "l"(p));
    return v;
}
__device__ __forceinline__ void bar_arrive(unsigned* p) {
    asm volatile("red.release.gpu.global.add.u32 [%0], 1;" :: "l"(p) : "memory");
}
__device__ __forceinline__ unsigned ld_acq(const unsigned* p) {
    unsigned v;
    asm volatile("ld.acquire.gpu.global.u32 %0, [%1];" : "=r"(v) : "l"(p) : "memory");
    return v;
}

__global__ void zero_state_kernel() {
    int i = blockIdx.x * blockDim.x + threadIdx.x;   // 65536 threads
    ((float*)g_h0)[i] = 0.f;
    ((float*)g_h1)[i] = 0.f;
    if (i < 2 * NB * NHD) { ((float*)g_hd0)[i] = 0.f; ((float*)g_hd1)[i] = 0.f; }
    if (i < 128) g_ebar[i] = 0u;
    else if (i < 256) g_dbar[i - 128] = 0u;
}

// SMEM float offsets (encoder)
#define E_W0X 0
#define E_W0H 4224
#define E_W1I 12544
#define E_W1H 20864
#define E_XS  29184
#define E_H0P 33408
#define E_H1P 41728
#define E_PRE 50048   /* [2 banks][2 L][32][33] : bank stride 2112, L stride 1056 */
#define E_CST 54272   /* [2][256] */
#define E_BIA 54784   /* [64] */
#define E_TOT 54848

// =================== persistent encoder ===================
// 128 CTAs = 4 groups x 32 CTAs; group owns 32 batch rows; CTA owns 8 units
// (x4 gates) of both layers. 512 threads: 256/layer; per layer:
//   bs = t&7 (batch lane), rgl = (t>>3)&3, kh = (t>>5)&3 (K interleave,
//   per-warp const), rgh = t>>7; thread tile = 4 rows x 4 batch.
__global__ void __launch_bounds__(512, 1) enc_persist(
    const float* __restrict__ x,
    const float* __restrict__ eW0, const float* __restrict__ eU0,
    const float* __restrict__ eb0, const float* __restrict__ ec0,
    const float* __restrict__ eW1, const float* __restrict__ eU1,
    const float* __restrict__ eb1, const float* __restrict__ ec1)
{
    extern __shared__ float sm[];
    const int tid = threadIdx.x;
    const int grp = blockIdx.x >> 5;
    const int cta = blockIdx.x & 31;
    const int bg  = grp * 32;
    const int ub  = cta * 8;
    unsigned* ebar = &g_ebar[grp * 32];

    // ---- load weights (rows = gate*8 + unit) ----
    for (int idx = tid; idx < 32 * 128; idx += 512) {
        int row = idx >> 7, k = idx & 127;
        int grow = (row >> 3) * NH + ub + (row & 7);
        sm[E_W0X + row * 132 + k] = eW0[grow * ND + k];
    }
    for (int idx = tid; idx < 32 * 256; idx += 512) {
        int row = idx >> 8, k = idx & 255;
        int grow = (row >> 3) * NH + ub + (row & 7);
        sm[E_W0H + row * 260 + k] = eU0[grow * NH + k];
        sm[E_W1I + row * 260 + k] = eW1[grow * NH + k];
        sm[E_W1H + row * 260 + k] = eU1[grow * NH + k];
    }
    if (tid < 32) {
        int grow = (tid >> 3) * NH + ub + (tid & 7);
        sm[E_BIA + tid]      = eb0[grow] + ec0[grow];
        sm[E_BIA + 32 + tid] = eb1[grow] + ec1[grow];
    }
    for (int idx = tid; idx < 512; idx += 512) sm[E_CST + idx] = 0.f;

    // ---- prologue staging (s = 0) ----
    for (int idx = tid; idx < 32 * 32; idx += 512) {
        int row = idx >> 5, c4 = (idx & 31) << 2;
        *(float4*)&sm[E_XS + row * 132 + c4] =
            __ldg((const float4*)&x[((bg + row) * NT + 0) * ND + c4]);
    }
    {
        const float* h0g = g_h0[1];
        const float* h1g = g_h1[0];
        for (int idx = tid; idx < 32 * 64; idx += 512) {
            int row = idx >> 6, c4 = (idx & 63) << 2;
            *(float4*)&sm[E_H0P + row * 260 + c4] = ldcg4(&h0g[(bg + row) * NH + c4]);
            *(float4*)&sm[E_H1P + row * 260 + c4] = ldcg4(&h1g[(bg + row) * NH + c4]);
        }
    }
    __syncthreads();

    const int L   = tid >> 8;
    const int t   = tid & 255;
    const int bs  = t & 7;
    const int rgl = (t >> 3) & 3;
    const int kh  = (t >> 5) & 3;
    const int rgh = t >> 7;
    const int r0  = (rgh * 4 + rgl) * 4;           // 4 rows r0..r0+3
    const int khb = 4 * kh;

    for (int s = 0; s <= NT; s++) {
        const bool act = (L == 0) ? (s < NT) : (s >= 1);
        ull acc[4][4][2] = {};
        if (act) {
            if (L == 0) {
                // x part: c = 16j + 4kh, j < 8
#pragma unroll
                for (int j = 0; j < 8; j++) {
                    int c = 16 * j + khb;
                    ulonglong2 w0 = *(const ulonglong2*)&sm[E_W0X + (r0 + 0) * 132 + c];
                    ulonglong2 w1 = *(const ulonglong2*)&sm[E_W0X + (r0 + 1) * 132 + c];
                    ulonglong2 w2 = *(const ulonglong2*)&sm[E_W0X + (r0 + 2) * 132 + c];
                    ulonglong2 w3 = *(const ulonglong2*)&sm[E_W0X + (r0 + 3) * 132 + c];
#pragma unroll
                    for (int i = 0; i < 4; i++) {
                        ulonglong2 a = *(const ulonglong2*)&sm[E_XS + (bs + 8 * i) * 132 + c];
                        fma2(acc[0][i][0], a.x, w0.x); fma2(acc[0][i][1], a.y, w0.y);
                        fma2(acc[1][i][0], a.x, w1.x); fma2(acc[1][i][1], a.y, w1.y);
                        fma2(acc[2][i][0], a.x, w2.x); fma2(acc[2][i][1], a.y, w2.y);
                        fma2(acc[3][i][0], a.x, w3.x); fma2(acc[3][i][1], a.y, w3.y);
                    }
                }
                // h part: c = 16j + 4kh, j < 16
#pragma unroll 4
                for (int j = 0; j < 16; j++) {
                    int c = 16 * j + khb;
                    ulonglong2 w0 = *(const ulonglong2*)&sm[E_W0H + (r0 + 0) * 260 + c];
                    ulonglong2 w1 = *(const ulonglong2*)&sm[E_W0H + (r0 + 1) * 260 + c];
                    ulonglong2 w2 = *(const ulonglong2*)&sm[E_W0H + (r0 + 2) * 260 + c];
                    ulonglong2 w3 = *(const ulonglong2*)&sm[E_W0H + (r0 + 3) * 260 + c];
#pragma unroll
                    for (int i = 0; i < 4; i++) {
                        ulonglong2 a = *(const ulonglong2*)&sm[E_H0P + (bs + 8 * i) * 260 + c];
                        fma2(acc[0][i][0], a.x, w0.x); fma2(acc[0][i][1], a.y, w0.y);
                        fma2(acc[1][i][0], a.x, w1.x); fma2(acc[1][i][1], a.y, w1.y);
                        fma2(acc[2][i][0], a.x, w2.x); fma2(acc[2][i][1], a.y, w2.y);
                        fma2(acc[3][i][0], a.x, w3.x); fma2(acc[3][i][1], a.y, w3.y);
                    }
                }
            } else {
#pragma unroll 4
                for (int j = 0; j < 16; j++) {
                    int c = 16 * j + khb;
                    ulonglong2 w0 = *(const ulonglong2*)&sm[E_W1I + (r0 + 0) * 260 + c];
                    ulonglong2 w1 = *(const ulonglong2*)&sm[E_W1I + (r0 + 1) * 260 + c];
                    ulonglong2 w2 = *(const ulonglong2*)&sm[E_W1I + (r0 + 2) * 260 + c];
                    ulonglong2 w3 = *(const ulonglong2*)&sm[E_W1I + (r0 + 3) * 260 + c];
#pragma unroll
                    for (int i = 0; i < 4; i++) {
                        ulonglong2 a = *(const ulonglong2*)&sm[E_H0P + (bs + 8 * i) * 260 + c];
                        fma2(acc[0][i][0], a.x, w0.x); fma2(acc[0][i][1], a.y, w0.y);
                        fma2(acc[1][i][0], a.x, w1.x); fma2(acc[1][i][1], a.y, w1.y);
                        fma2(acc[2][i][0], a.x, w2.x); fma2(acc[2][i][1], a.y, w2.y);
                        fma2(acc[3][i][0], a.x, w3.x); fma2(acc[3][i][1], a.y, w3.y);
                    }
                }
#pragma unroll 4
                for (int j = 0; j < 16; j++) {
                    int c = 16 * j + khb;
                    ulonglong2 w0 = *(const ulonglong2*)&sm[E_W1H + (r0 + 0) * 260 + c];
                    ulonglong2 w1 = *(const ulonglong2*)&sm[E_W1H + (r0 + 1) * 260 + c];
                    ulonglong2 w2 = *(const ulonglong2*)&sm[E_W1H + (r0 + 2) * 260 + c];
                    ulonglong2 w3 = *(const ulonglong2*)&sm[E_W1H + (r0 + 3) * 260 + c];
#pragma unroll
                    for (int i = 0; i < 4; i++) {
                        ulonglong2 a = *(const ulonglong2*)&sm[E_H1P + (bs + 8 * i) * 260 + c];
                        fma2(acc[0][i][0], a.x, w0.x); fma2(acc[0][i][1], a.y, w0.y);
                        fma2(acc[1][i][0], a.x, w1.x); fma2(acc[1][i][1], a.y, w1.y);
                        fma2(acc[2][i][0], a.x, w2.x); fma2(acc[2][i][1], a.y, w2.y);
                        fma2(acc[3][i][0], a.x, w3.x); fma2(acc[3][i][1], a.y, w3.y);
                    }
                }
            }
        }

        // ---- merge partials into pre banks ----
        float pv[4][4];
#pragma unroll
        for (int ri = 0; ri < 4; ri++)
#pragma unroll
            for (int i = 0; i < 4; i++)
                pv[ri][i] = hadd2(acc[ri][i][0]) + hadd2(acc[ri][i][1]);

        float* pb = sm + E_PRE + (kh & 1) * 2112 + L * 1056;
        if (act && (kh >> 1) == 0) {
#pragma unroll
            for (int ri = 0; ri < 4; ri++)
#pragma unroll
                for (int i = 0; i < 4; i++)
                    pb[(r0 + ri) * 33 + bs + 8 * i] = pv[ri][i];
        }
        __syncthreads();
        if (act && (kh >> 1) == 1) {
#pragma unroll
            for (int ri = 0; ri < 4; ri++)
#pragma unroll
                for (int i = 0; i < 4; i++)
                    pb[(r0 + ri) * 33 + bs + 8 * i] += pv[ri][i];
        }
        __syncthreads();

        // ---- combine + state update ----
        {
            const int cl = tid >> 8, u = tid & 7, b = (tid >> 3) & 31;
            bool ok = (cl == 0) ? (s < NT) : (s >= 1);
            if (ok) {
                const float* pa = sm + E_PRE + cl * 1056;          // bank 0
                const float* pc = sm + E_PRE + 2112 + cl * 1056;   // bank 1
                float gi = pa[(0 * 8 + u) * 33 + b] + pc[(0 * 8 + u) * 33 + b] + sm[E_BIA + cl * 32 + 0 * 8 + u];
                float gf = pa[(1 * 8 + u) * 33 + b] + pc[(1 * 8 + u) * 33 + b] + sm[E_BIA + cl * 32 + 1 * 8 + u];
                float gg = pa[(2 * 8 + u) * 33 + b] + pc[(2 * 8 + u) * 33 + b] + sm[E_BIA + cl * 32 + 2 * 8 + u];
                float go = pa[(3 * 8 + u) * 33 + b] + pc[(3 * 8 + u) * 33 + b] + sm[E_BIA + cl * 32 + 3 * 8 + u];
                float c  = sm[E_CST + cl * 256 + b * 8 + u];
                float cv = sigf(gf) * c + sigf(gi) * tanhf(gg);
                sm[E_CST + cl * 256 + b * 8 + u] = cv;
                float hv = sigf(go) * tanhf(cv);
                int gidx = (bg + b) * NH + ub + u;
                if (cl == 0) g_h0[s & 1][gidx] = hv;
                else         g_h1[(s - 1) & 1][gidx] = hv;
            }
        }
        __syncthreads();
        if (s == NT) break;

        // ---- arrive; overlap x staging; wait; stage h ----
        if (tid == 0) bar_arrive(ebar);
        if (s + 1 < NT) {
            for (int idx = tid; idx < 32 * 32; idx += 512) {
                int row = idx >> 5, c4 = (idx & 31) << 2;
                *(float4*)&sm[E_XS + row * 132 + c4] =
                    __ldg((const float4*)&x[((bg + row) * NT + (s + 1)) * ND + c4]);
            }
        }
        if (tid == 0) {
            unsigned target = 32u * (unsigned)(s + 1);
            while (ld_acq(ebar) < target) { }
        }
        __syncthreads();
        {
            const float* h0g = g_h0[s & 1];
            const float* h1g = g_h1[(s + 1) & 1];
            for (int idx = tid; idx < 32 * 64; idx += 512) {
                int row = idx >> 6, c4 = (idx & 63) << 2;
                *(float4*)&sm[E_H0P + row * 260 + c4] = ldcg4(&h0g[(bg + row) * NH + c4]);
                *(float4*)&sm[E_H1P + row * 260 + c4] = ldcg4(&h1g[(bg + row) * NH + c4]);
            }
        }
        __syncthreads();
    }
}

// ---- decoder L0 constant input projection ----
__global__ void xwd0_kernel(const float* __restrict__ dW0,
                            const float* __restrict__ db0,
                            const float* __restrict__ dc0)
{
    int idx = blockIdx.x * blockDim.x + threadIdx.x;   // 65536
    int b = idx >> 9, gd = idx & 511;
    const float* hb = &g_h1[1][b * NH];                // h1[NT-1] in buffer 1
    const float* wr = dW0 + gd * NH;
    ull a0 = 0ULL, a1 = 0ULL;
#pragma unroll 4
    for (int k = 0; k < NH; k += 4) {
        ulonglong2 hv = *(const ulonglong2*)&hb[k];
        ulonglong2 wv = *(const ulonglong2*)&wr[k];
        fma2(a0, hv.x, wv.x); fma2(a1, hv.y, wv.y);
    }
    g_xwd0[idx] = hadd2(a0) + hadd2(a1) + db0[gd] + dc0[gd];
}

// SMEM float offsets (decoder)
#define D_W0H 0
#define D_W1I 2112
#define D_W1H 4224
#define D_H0P 6336
#define D_H1P 10560
#define D_XW  14784   /* [32][17] */
#define D_PRE 15328   /* [4 banks][2 L][16][33] : bank 1056, L 528 */
#define D_CST 19552   /* [2][128] */
#define D_BIA 19808   /* [16] */
#define D_TOT 19824

// =================== persistent decoder ===================
// per layer: bs = t&7, rgrp = (t>>3)&3, kh = t>>5 (8-way K interleave).
__global__ void __launch_bounds__(512, 1) dec_persist(
    const float* __restrict__ dU0,
    const float* __restrict__ dW1, const float* __restrict__ dU1,
    const float* __restrict__ db1, const float* __restrict__ dc1,
    float* __restrict__ out)
{
    extern __shared__ float sm[];
    const int tid = threadIdx.x;
    const int grp = blockIdx.x >> 5;
    const int cta = blockIdx.x & 31;
    const int bg  = grp * 32;
    const int ub  = cta * 4;
    unsigned* dbar = &g_dbar[grp * 32];

    for (int idx = tid; idx < 16 * 128; idx += 512) {
        int row = idx >> 7, k = idx & 127;
        int grow = (row >> 2) * NHD + ub + (row & 3);
        sm[D_W0H + row * 132 + k] = dU0[grow * NHD + k];
        sm[D_W1I + row * 132 + k] = dW1[grow * NHD + k];
        sm[D_W1H + row * 132 + k] = dU1[grow * NHD + k];
    }
    if (tid < 16) {
        int grow = (tid >> 2) * NHD + ub + (tid & 3);
        sm[D_BIA + tid] = db1[grow] + dc1[grow];
    }
    {
        int b = tid >> 4, row = tid & 15;
        sm[D_XW + b * 17 + row] =
            g_xwd0[(bg + b) * 4 * NHD + (row >> 2) * NHD + ub + (row & 3)];
    }
    for (int idx = tid; idx < 256; idx += 512) sm[D_CST + idx] = 0.f;
    {
        const float* h0g = g_hd0[1];
        const float* h1g = g_hd1[0];
        for (int idx = tid; idx < 32 * 32; idx += 512) {
            int row = idx >> 5, c4 = (idx & 31) << 2;
            *(float4*)&sm[D_H0P + row * 132 + c4] = ldcg4(&h0g[(bg + row) * NHD + c4]);
            *(float4*)&sm[D_H1P + row * 132 + c4] = ldcg4(&h1g[(bg + row) * NHD + c4]);
        }
    }
    __syncthreads();

    const int L   = tid >> 8;
    const int t   = tid & 255;
    const int bs  = t & 7;
    const int r0  = ((t >> 3) & 3) * 4;
    const int kh  = t >> 5;            // 0..7
    const int khb = 4 * kh;

    for (int s = 0; s <= NT; s++) {
        const bool act = (L == 0) ? (s < NT) : (s >= 1);
        ull acc[4][4][2] = {};
        if (act) {
            if (L == 0) {
#pragma unroll
                for (int j = 0; j < 4; j++) {
                    int c = 32 * j + khb;
                    ulonglong2 w0 = *(const ulonglong2*)&sm[D_W0H + (r0 + 0) * 132 + c];
                    ulonglong2 w1 = *(const ulonglong2*)&sm[D_W0H + (r0 + 1) * 132 + c];
                    ulonglong2 w2 = *(const ulonglong2*)&sm[D_W0H + (r0 + 2) * 132 + c];
                    ulonglong2 w3 = *(const ulonglong2*)&sm[D_W0H + (r0 + 3) * 132 + c];
#pragma unroll
                    for (int i = 0; i < 4; i++) {
                        ulonglong2 a = *(const ulonglong2*)&sm[D_H0P + (bs + 8 * i) * 132 + c];
                        fma2(acc[0][i][0], a.x, w0.x); fma2(acc[0][i][1], a.y, w0.y);
                        fma2(acc[1][i][0], a.x, w1.x); fma2(acc[1][i][1], a.y, w1.y);
                        fma2(acc[2][i][0], a.x, w2.x); fma2(acc[2][i][1], a.y, w2.y);
                        fma2(acc[3][i][0], a.x, w3.x); fma2(acc[3][i][1], a.y, w3.y);
                    }
                }
            } else {
#pragma unroll
                for (int j = 0; j < 4; j++) {
                    int c = 32 * j + khb;
                    ulonglong2 w0 = *(const ulonglong2*)&sm[D_W1I + (r0 + 0) * 132 + c];
                    ulonglong2 w1 = *(const ulonglong2*)&sm[D_W1I + (r0 + 1) * 132 + c];
                    ulonglong2 w2 = *(const ulonglong2*)&sm[D_W1I + (r0 + 2) * 132 + c];
                    ulonglong2 w3 = *(const ulonglong2*)&sm[D_W1I + (r0 + 3) * 132 + c];
#pragma unroll
                    for (int i = 0; i < 4; i++) {
                        ulonglong2 a = *(const ulonglong2*)&sm[D_H0P + (bs + 8 * i) * 132 + c];
                        fma2(acc[0][i][0], a.x, w0.x); fma2(acc[0][i][1], a.y, w0.y);
                        fma2(acc[1][i][0], a.x, w1.x); fma2(acc[1][i][1], a.y, w1.y);
                        fma2(acc[2][i][0], a.x, w2.x); fma2(acc[2][i][1], a.y, w2.y);
                        fma2(acc[3][i][0], a.x, w3.x); fma2(acc[3][i][1], a.y, w3.y);
                    }
                }
#pragma unroll
                for (int j = 0; j < 4; j++) {
                    int c = 32 * j + khb;
                    ulonglong2 w0 = *(const ulonglong2*)&sm[D_W1H + (r0 + 0) * 132 + c];
                    ulonglong2 w1 = *(const ulonglong2*)&sm[D_W1H + (r0 + 1) * 132 + c];
                    ulonglong2 w2 = *(const ulonglong2*)&sm[D_W1H + (r0 + 2) * 132 + c];
                    ulonglong2 w3 = *(const ulonglong2*)&sm[D_W1H + (r0 + 3) * 132 + c];
#pragma unroll
                    for (int i = 0; i < 4; i++) {
                        ulonglong2 a = *(const ulonglong2*)&sm[D_H1P + (bs + 8 * i) * 132 + c];
                        fma2(acc[0][i][0], a.x, w0.x); fma2(acc[0][i][1], a.y, w0.y);
                        fma2(acc[1][i][0], a.x, w1.x); fma2(acc[1][i][1], a.y, w1.y);
                        fma2(acc[2][i][0], a.x, w2.x); fma2(acc[2][i][1], a.y, w2.y);
                        fma2(acc[3][i][0], a.x, w3.x); fma2(acc[3][i][1], a.y, w3.y);
                    }
                }
            }
        }

        float pv[4][4];
#pragma unroll
        for (int ri = 0; ri < 4; ri++)
#pragma unroll
            for (int i = 0; i < 4; i++)
                pv[ri][i] = hadd2(acc[ri][i][0]) + hadd2(acc[ri][i][1]);

        float* pb = sm + D_PRE + (kh & 3) * 1056 + L * 528;
        if (act && (kh >> 2) == 0) {
#pragma unroll
            for (int ri = 0; ri < 4; ri++)
#pragma unroll
                for (int i = 0; i < 4; i++)
                    pb[(r0 + ri) * 33 + bs + 8 * i] = pv[ri][i];
        }
        __syncthreads();
        if (act && (kh >> 2) == 1) {
#pragma unroll
            for (int ri = 0; ri < 4; ri++)
#pragma unroll
                for (int i = 0; i < 4; i++)
                    pb[(r0 + ri) * 33 + bs + 8 * i] += pv[ri][i];
        }
        __syncthreads();

        if (tid < 256) {
            const int cl = tid >> 7, u = tid & 3, b = (tid >> 2) & 31;
            bool ok = (cl == 0) ? (s < NT) : (s >= 1);
            if (ok) {
                float g4[4];
#pragma unroll
                for (int g = 0; g < 4; g++) {
                    int r = g * 4 + u;
                    float v = sm[D_PRE + 0 * 1056 + cl * 528 + r * 33 + b]
                            + sm[D_PRE + 1 * 1056 + cl * 528 + r * 33 + b]
                            + sm[D_PRE + 2 * 1056 + cl * 528 + r * 33 + b]
                            + sm[D_PRE + 3 * 1056 + cl * 528 + r * 33 + b];
                    v += (cl == 0) ? sm[D_XW + b * 17 + r] : sm[D_BIA + r];
                    g4[g] = v;
                }
                float c  = sm[D_CST + cl * 128 + b * 4 + u];
                float cv = sigf(g4[1]) * c + sigf(g4[0]) * tanhf(g4[2]);
                sm[D_CST + cl * 128 + b * 4 + u] = cv;
                float hv = sigf(g4[3]) * tanhf(cv);
                int gidx = (bg + b) * NHD + ub + u;
                if (cl == 0) g_hd0[s & 1][gidx] = hv;
                else {
                    g_hd1[(s - 1) & 1][gidx] = hv;
                    out[((bg + b) * NT + (s - 1)) * ND + ub + u] = hv;
                }
            }
        }
        __syncthreads();
        if (s == NT) break;

        if (tid == 0) {
            bar_arrive(dbar);
            unsigned target = 32u * (unsigned)(s + 1);
            while (ld_acq(dbar) < target) { }
        }
        __syncthreads();
        {
            const float* h0g = g_hd0[s & 1];
            const float* h1g = g_hd1[(s + 1) & 1];
            for (int idx = tid; idx < 32 * 32; idx += 512) {
                int row = idx >> 5, c4 = (idx & 31) << 2;
                *(float4*)&sm[D_H0P + row * 132 + c4] = ldcg4(&h0g[(bg + row) * NHD + c4]);
                *(float4*)&sm[D_H1P + row * 132 + c4] = ldcg4(&h1g[(bg + row) * NHD + c4]);
            }
        }
        __syncthreads();
    }
}

extern "C" void kernel_launch(void* const* d_in, const int* in_sizes, int n_in,
                              void* d_out, int out_size)
{
    (void)in_sizes; (void)n_in; (void)out_size;
    const float* x   = (const float*)d_in[0];
    const float* eW0 = (const float*)d_in[1];
    const float* eU0 = (const float*)d_in[2];
    const float* eb0 = (const float*)d_in[3];
    const float* ec0 = (const float*)d_in[4];
    const float* eW1 = (const float*)d_in[5];
    const float* eU1 = (const float*)d_in[6];
    const float* eb1 = (const float*)d_in[7];
    const float* ec1 = (const float*)d_in[8];
    const float* dW0 = (const float*)d_in[9];
    const float* dU0 = (const float*)d_in[10];
    const float* db0 = (const float*)d_in[11];
    const float* dc0 = (const float*)d_in[12];
    const float* dW1 = (const float*)d_in[13];
    const float* dU1 = (const float*)d_in[14];
    const float* db1 = (const float*)d_in[15];
    const float* dc1 = (const float*)d_in[16];
    float* out = (float*)d_out;

    const int ENC_SMEM = E_TOT * 4;   // 219392 B
    const int DEC_SMEM = D_TOT * 4;   // 79296 B

    static bool attr_done = false;
    if (!attr_done) {
        cudaFuncSetAttribute(enc_persist, cudaFuncAttributeMaxDynamicSharedMemorySize, ENC_SMEM);
        cudaFuncSetAttribute(dec_persist, cudaFuncAttributeMaxDynamicSharedMemorySize, DEC_SMEM);
        attr_done = true;
    }

    zero_state_kernel<<<128, 512>>>();
    enc_persist<<<128, 512, ENC_SMEM>>>(x, eW0, eU0, eb0, ec0, eW1, eU1, eb1, ec1);
    xwd0_kernel<<<128, 512>>>(dW0, db0, dc0);
    dec_persist<<<128, 512, DEC_SMEM>>>(dU0, dW1, dU1, db1, dc1, out);
}